// round 5
// baseline (speedup 1.0000x reference)
#include <cuda_runtime.h>
#include <math.h>

#define NN 50000
#define EE 800000
#define EMB 64
#define ATOM_F 32
#define BOND_F 16
#define NLAYER 5
#define CHUNK 32

typedef unsigned long long ull;

// ---------------- scratch (device globals; no allocation allowed) ----------------
__device__ __align__(16) float g_h[NN * EMB];
__device__ __align__(16) float g_aggr[NN * EMB];
__device__ __align__(16) float g_hn[NN * EMB];
__device__ __align__(16) float g_sea[NN * BOND_F];
__device__ __align__(16) float g_deg[NN];
__device__ __align__(16) float g_stats[2 * 2 * EMB];  // parity-double-buffered BN sums

// CSR by destination (built once per launch)
__device__ int g_ideg[NN];
__device__ int g_rowptr[NN + 1];
__device__ int g_cursor[NN];
__device__ __align__(8) int2 g_edge[EE];  // {src, dst} in CSR (dst-sorted) order
__device__ int g_ceid[EE];                // original edge id per CSR slot
__device__ int g_bsum[256];
__device__ int g_boff[256];

// ---------------- f32x2 packed helpers ----------------
__device__ __forceinline__ void fma2(ull& d, ull a, ull b) {
    asm("fma.rn.f32x2 %0, %1, %2, %0;" : "+l"(d) : "l"(a), "l"(b));
}
__device__ __forceinline__ ull add2(ull a, ull b) {
    ull d; asm("add.rn.f32x2 %0, %1, %2;" : "=l"(d) : "l"(a), "l"(b)); return d;
}
__device__ __forceinline__ ull mul2(ull a, ull b) {
    ull d; asm("mul.rn.f32x2 %0, %1, %2;" : "=l"(d) : "l"(a), "l"(b)); return d;
}
__device__ __forceinline__ ull dup2(float x) {
    ull d; asm("mov.b64 %0, {%1, %1};" : "=l"(d) : "f"(x)); return d;
}
__device__ __forceinline__ float2 unpack2(ull v) {
    float2 r; asm("mov.b64 {%0, %1}, %2;" : "=f"(r.x), "=f"(r.y) : "l"(v)); return r;
}
__device__ __forceinline__ float mishf(float v) {
    return v * tanhf(log1pf(expf(v)));
}
__device__ __forceinline__ void flush_red(int dst, int lane, float2 acc) {
    float* p = g_aggr + (size_t)dst * EMB + lane * 2;
    unsigned long long gp = (unsigned long long)__cvta_generic_to_global(p);
    asm volatile("red.global.add.v2.f32 [%0], {%1, %2};"
                 :: "l"(gp), "f"(acc.x), "f"(acc.y) : "memory");
}

// ---------------- kernels ----------------

// h = x @ Wemb^T
__global__ void k_embed(const float* __restrict__ x, const float* __restrict__ Wemb) {
    __shared__ float sW[EMB * ATOM_F];
    for (int i = threadIdx.x; i < EMB * ATOM_F; i += blockDim.x) sW[i] = Wemb[i];
    __syncthreads();
    int node = blockIdx.x * blockDim.x + threadIdx.x;
    if (node >= NN) return;
    float4 xv[8];
    const float4* x4 = (const float4*)(x + (size_t)node * ATOM_F);
#pragma unroll
    for (int f = 0; f < 8; f++) xv[f] = __ldg(&x4[f]);
    float4* out4 = (float4*)(g_h + (size_t)node * EMB);
    for (int j = 0; j < EMB; j += 4) {
        float accs[4];
#pragma unroll
        for (int c = 0; c < 4; c++) {
            const float4* w = (const float4*)(sW + (j + c) * ATOM_F);
            float a = 0.f, b = 0.f;
#pragma unroll
            for (int f = 0; f < 8; f++) {
                float4 wv = w[f];
                a = fmaf(xv[f].x, wv.x, a);
                b = fmaf(xv[f].y, wv.y, b);
                a = fmaf(xv[f].z, wv.z, a);
                b = fmaf(xv[f].w, wv.w, b);
            }
            accs[c] = a + b;
        }
        out4[j >> 2] = make_float4(accs[0], accs[1], accs[2], accs[3]);
    }
}

// zero: ideg, aggr, all BN stat buffers   (grid covers NN*EMB/4 float4s)
__global__ void k_zero_init() {
    int t = blockIdx.x * blockDim.x + threadIdx.x;
    if (t < NN) g_ideg[t] = 0;
    if (t < 4 * EMB) g_stats[t] = 0.f;
    if (t < NN * (EMB / 4)) ((float4*)g_aggr)[t] = make_float4(0.f, 0.f, 0.f, 0.f);
}

__global__ void k_hist(const int* __restrict__ ei) {
    int e = blockIdx.x * blockDim.x + threadIdx.x;
    if (e >= EE) return;
    atomicAdd(&g_ideg[__ldg(&ei[EE + e])], 1);
}

// multi-block exclusive scan: phase 1 (per-block scan + block sums)
__global__ void k_scan1() {
    __shared__ int s[256];
    int tid = threadIdx.x;
    int i = blockIdx.x * 256 + tid;
    int v = (i < NN) ? g_ideg[i] : 0;
    s[tid] = v;
    __syncthreads();
#pragma unroll
    for (int off = 1; off < 256; off <<= 1) {
        int add = (tid >= off) ? s[tid - off] : 0;
        __syncthreads();
        s[tid] += add;
        __syncthreads();
    }
    if (i < NN) g_rowptr[i] = s[tid] - v;
    if (tid == 255) g_bsum[blockIdx.x] = s[255];
}

__global__ void k_scan2() {
    __shared__ int s[256];
    int tid = threadIdx.x;
    const int nb = (NN + 255) / 256;
    int v = (tid < nb) ? g_bsum[tid] : 0;
    s[tid] = v;
    __syncthreads();
#pragma unroll
    for (int off = 1; off < 256; off <<= 1) {
        int add = (tid >= off) ? s[tid - off] : 0;
        __syncthreads();
        s[tid] += add;
        __syncthreads();
    }
    g_boff[tid] = s[tid] - v;
}

__global__ void k_scan3() {
    int i = blockIdx.x * 256 + threadIdx.x;
    if (i < NN) {
        int r = g_rowptr[i] + g_boff[blockIdx.x];
        g_rowptr[i] = r;
        g_cursor[i] = r;
    }
    if (i == 0) g_rowptr[NN] = EE;
}

__global__ void k_fill(const int* __restrict__ ei) {
    int e = blockIdx.x * blockDim.x + threadIdx.x;
    if (e >= EE) return;
    int dst = __ldg(&ei[EE + e]);
    int src = __ldg(&ei[e]);
    int pos = atomicAdd(&g_cursor[dst], 1);
    g_edge[pos] = make_int2(src, dst);
    g_ceid[pos] = e;
}

// sea[n] = sum of incident edge_attr; deg[n] = count   (16 threads per node)
__global__ void k_pre(const float* __restrict__ ea) {
    int t = blockIdx.x * blockDim.x + threadIdx.x;
    int n = t >> 4;
    if (n >= NN) return;
    int lane = t & 15;
    int beg = g_rowptr[n], end = g_rowptr[n + 1];
    if (lane == 0) g_deg[n] = (float)(end - beg);
    float acc = 0.f;
    for (int i = beg; i < end; i++) {
        int e = __ldg(&g_ceid[i]);
        acc += __ldg(&ea[(size_t)e * BOND_F + lane]);
    }
    g_sea[(size_t)n * BOND_F + lane] = acc;
}

// segmented edge-parallel aggregation: each warp owns CHUNK CSR slots,
// accumulates h[src] runs per dst in registers, flushes at boundaries with
// vector red. g_aggr must be pre-zeroed; self-loop is added in k_mlp.
__global__ void __launch_bounds__(256) k_aggr_seg() {
    int w = (blockIdx.x * blockDim.x + threadIdx.x) >> 5;
    int lane = threadIdx.x & 31;
    int base = w * CHUNK;            // EE % CHUNK == 0, grid sized exactly
    const float2* h2 = (const float2*)g_h;
    int2 e = __ldg(&g_edge[base]);
    int cur = e.y;
    float2 acc = make_float2(0.f, 0.f);
#pragma unroll 4
    for (int i = 0; i < CHUNK; i++) {
        int2 en = e;
        if (i + 1 < CHUNK) en = __ldg(&g_edge[base + i + 1]);
        float2 v = __ldg(&h2[(size_t)e.x * 32 + lane]);
        if (e.y != cur) {
            flush_red(cur, lane, acc);
            acc = make_float2(0.f, 0.f);
            cur = e.y;
        }
        acc.x += v.x; acc.y += v.y;
        e = en;
    }
    flush_red(cur, lane, acc);
}

// fused MLP (packed f32x2) + fused BN statistics.
// z = h + aggr + Sea@We^T + (deg+1)*be ; hid = relu(z@W1^T + b1) ; hn = hid@W2^T
// (b2 dropped: cancels under BatchNorm mean subtraction)
__global__ void __launch_bounds__(128, 2) k_mlp(
    const float* __restrict__ W1, const float* __restrict__ b1,
    const float* __restrict__ W2, const float* __restrict__ We,
    const float* __restrict__ be, int l)
{
    extern __shared__ float sm[];
    float* sW1  = sm;                 // [128][64]
    float* sW2T = sm + 8192;          // [128][64]
    float* sWeT = sm + 16384;         // [16][64]
    float* sb1  = sm + 17408;         // [128]
    float* sbe  = sm + 17536;         // [64]
    float* sred = sm + 17600;         // [4][128]

    int tid = threadIdx.x;
    const float* W1l = W1 + (size_t)l * 8192;
    const float* W2l = W2 + (size_t)l * 8192;
    for (int i = tid; i < 8192; i += 128) sW1[i] = W1l[i];
    for (int i = tid; i < 8192; i += 128) {
        int j = i >> 7, k = i & 127;
        sW2T[k * 64 + j] = W2l[i];
    }
    for (int i = tid; i < 1024; i += 128) {
        int q = i >> 6, j = i & 63;
        sWeT[i] = We[(size_t)l * 1024 + j * 16 + q];
    }
    if (tid < 128) sb1[tid] = b1[(size_t)l * 128 + tid];
    if (tid < 64)  sbe[tid] = be[(size_t)l * 64 + tid];
    __syncthreads();

    int node = blockIdx.x * 128 + tid;
    const bool valid = (node < NN);
    int nc = valid ? node : 0;

    // ---- prologue: z = aggr + h_self (packed) ----
    ull z2[32];
    {
        const ull* a2 = (const ull*)(g_aggr + (size_t)nc * EMB);
        const ull* s2 = (const ull*)(g_h + (size_t)nc * EMB);
#pragma unroll
        for (int p = 0; p < 32; p++) z2[p] = add2(a2[p], s2[p]);
    }
    {
        ull dp2 = dup2(g_deg[nc] + 1.0f);
        const ull* be2 = (const ull*)sbe;
#pragma unroll
        for (int p = 0; p < 32; p++) fma2(z2[p], dp2, be2[p]);
    }
    {
        float seav[16];
        const float4* sr = (const float4*)(g_sea + (size_t)nc * BOND_F);
#pragma unroll
        for (int q4 = 0; q4 < 4; q4++) {
            float4 v = sr[q4];
            seav[q4 * 4 + 0] = v.x; seav[q4 * 4 + 1] = v.y;
            seav[q4 * 4 + 2] = v.z; seav[q4 * 4 + 3] = v.w;
        }
#pragma unroll
        for (int q = 0; q < 16; q++) {
            ull sq = dup2(seav[q]);
            const ull* wq = (const ull*)(sWeT + q * 64);
#pragma unroll
            for (int p = 0; p < 32; p++) fma2(z2[p], sq, wq[p]);
        }
    }

    // ---- main loop over hidden units ----
    ull hn2[32];
#pragma unroll
    for (int p = 0; p < 32; p++) hn2[p] = 0ull;

#pragma unroll 2
    for (int k = 0; k < 128; k++) {
        const ulonglong2* wr = (const ulonglong2*)(sW1 + (k << 6));
        ull a = 0ull, b = 0ull, c = 0ull, d = 0ull;
#pragma unroll
        for (int p = 0; p < 8; p++) {
            ulonglong2 wA = wr[2 * p];
            ulonglong2 wB = wr[2 * p + 1];
            fma2(a, z2[4 * p + 0], wA.x);
            fma2(b, z2[4 * p + 1], wA.y);
            fma2(c, z2[4 * p + 2], wB.x);
            fma2(d, z2[4 * p + 3], wB.y);
        }
        float2 s = unpack2(add2(add2(a, b), add2(c, d)));
        float acc = fmaxf((s.x + s.y) + sb1[k], 0.0f);
        ull av = dup2(acc);
        const ulonglong2* w2r = (const ulonglong2*)(sW2T + (k << 6));
#pragma unroll
        for (int p = 0; p < 16; p++) {
            ulonglong2 w = w2r[p];
            fma2(hn2[2 * p + 0], av, w.x);
            fma2(hn2[2 * p + 1], av, w.y);
        }
    }

    if (valid) {
        ulonglong2* o = (ulonglong2*)(g_hn + (size_t)node * EMB);
#pragma unroll
        for (int p = 0; p < 16; p++)
            o[p] = make_ulonglong2(hn2[2 * p], hn2[2 * p + 1]);
    }

    // ---- fused BN statistics (packed warp reduction) ----
    int lane = tid & 31, wrp = tid >> 5;
#pragma unroll
    for (int p = 0; p < 32; p++) {
        ull s2 = valid ? hn2[p] : 0ull;
        ull q2 = mul2(s2, s2);
#pragma unroll
        for (int off = 16; off; off >>= 1) {
            s2 = add2(s2, __shfl_down_sync(0xffffffffu, s2, off));
            q2 = add2(q2, __shfl_down_sync(0xffffffffu, q2, off));
        }
        if (lane == 0) {
            float2 sv = unpack2(s2), qv = unpack2(q2);
            sred[wrp * 128 + 2 * p]     = sv.x;
            sred[wrp * 128 + 2 * p + 1] = sv.y;
            sred[wrp * 128 + 64 + 2 * p]     = qv.x;
            sred[wrp * 128 + 64 + 2 * p + 1] = qv.y;
        }
    }
    __syncthreads();
    if (tid < 128) {
        float v = sred[tid] + sred[128 + tid] + sred[256 + tid] + sred[384 + tid];
        atomicAdd(&g_stats[((l & 1) << 7) + tid], v);
    }
}

// BN (batch stats) + optional mish; writes g_h or d_out.
// Also zeroes g_aggr and the other-parity stats buffer for the next layer.
__global__ void k_finalize(const float* __restrict__ gamma, const float* __restrict__ beta,
                           int l, int domish, float* __restrict__ out)
{
    int t = blockIdx.x * blockDim.x + threadIdx.x;
    if (blockIdx.x == 0 && threadIdx.x < 128)
        g_stats[(((l + 1) & 1) << 7) + threadIdx.x] = 0.f;
    if (t >= NN * (EMB / 4)) return;
    int j4 = (t & 15) * 4;
    const float* st = g_stats + ((l & 1) << 7);
    float4 v = ((const float4*)g_hn)[t];
    float vv[4] = {v.x, v.y, v.z, v.w};
    float r[4];
    const float inv_n = 1.0f / (float)NN;
#pragma unroll
    for (int c = 0; c < 4; c++) {
        int j = j4 + c;
        float s = st[j], q = st[64 + j];
        float mu = s * inv_n;
        float var = fmaf(q, inv_n, -mu * mu);
        float inv = rsqrtf(var + 1e-5f);
        float val = (vv[c] - mu) * inv * __ldg(&gamma[l * 64 + j]) + __ldg(&beta[l * 64 + j]);
        if (domish) val = mishf(val);
        r[c] = val;
    }
    float4 o = make_float4(r[0], r[1], r[2], r[3]);
    if (out) ((float4*)out)[t] = o;
    else     ((float4*)g_h)[t] = o;
    ((float4*)g_aggr)[t] = make_float4(0.f, 0.f, 0.f, 0.f);  // for next layer
}

// ---------------- launch ----------------
extern "C" void kernel_launch(void* const* d_in, const int* in_sizes, int n_in,
                              void* d_out, int out_size)
{
    const float* x     = (const float*)d_in[0];
    const float* ea    = (const float*)d_in[1];
    const float* Wemb  = (const float*)d_in[2];
    const float* W1    = (const float*)d_in[3];
    const float* b1    = (const float*)d_in[4];
    const float* W2    = (const float*)d_in[5];
    // d_in[6] = b2 : provably cancelled by BatchNorm mean subtraction
    const float* We    = (const float*)d_in[7];
    const float* be    = (const float*)d_in[8];
    const float* gamma = (const float*)d_in[9];
    const float* beta  = (const float*)d_in[10];
    const int*   ei    = (const int*)d_in[11];
    float* out = (float*)d_out;

    const int MLP_SMEM = (8192 + 8192 + 1024 + 128 + 64 + 512) * 4; // 72448 B
    cudaFuncSetAttribute(k_mlp, cudaFuncAttributeMaxDynamicSharedMemorySize, MLP_SMEM);

    const int NB = (NN + 255) / 256;       // 196
    const int FB = (NN * (EMB / 4) + 255) / 256;  // 3125

    k_embed<<<(NN + 127) / 128, 128>>>(x, Wemb);

    // CSR build (once) + zero aggr/stats
    k_zero_init<<<FB, 256>>>();
    k_hist<<<(EE + 255) / 256, 256>>>(ei);
    k_scan1<<<NB, 256>>>();
    k_scan2<<<1, 256>>>();
    k_scan3<<<NB, 256>>>();
    k_fill<<<(EE + 255) / 256, 256>>>(ei);
    k_pre<<<(NN * 16 + 255) / 256, 256>>>(ea);

    const int AGGR_BLOCKS = (EE / CHUNK) * 32 / 256;  // 3125

    for (int l = 0; l < NLAYER; l++) {
        k_aggr_seg<<<AGGR_BLOCKS, 256>>>();
        k_mlp<<<(NN + 127) / 128, 128, MLP_SMEM>>>(W1, b1, W2, We, be, l);
        k_finalize<<<FB, 256>>>(
            gamma, beta, l, (l < NLAYER - 1) ? 1 : 0,
            (l == NLAYER - 1) ? out : nullptr);
    }
}

// round 6
// speedup vs baseline: 1.0675x; 1.0675x over previous
#include <cuda_runtime.h>
#include <math.h>

#define NN 50000
#define EE 800000
#define EMB 64
#define ATOM_F 32
#define BOND_F 16
#define NLAYER 5

typedef unsigned long long ull;

// ---------------- scratch (device globals; no allocation allowed) ----------------
__device__ __align__(16) float g_h[NN * EMB];
__device__ __align__(16) float g_aggr[NN * EMB];
__device__ __align__(16) float g_hn[NN * EMB];
__device__ __align__(16) float g_sea[NN * BOND_F];
__device__ __align__(16) float g_deg[NN];
__device__ __align__(16) float g_stats[2 * 2 * EMB];  // parity-double-buffered BN sums

// CSR by destination (built once per launch)
__device__ int g_ideg[NN];
__device__ int g_rowptr[NN + 1];
__device__ int g_cursor[NN];
__device__ int g_csrc[EE];
__device__ int g_ceid[EE];
__device__ int g_bsum[256];
__device__ int g_boff[256];

// ---------------- f32x2 packed helpers ----------------
__device__ __forceinline__ void fma2(ull& d, ull a, ull b) {
    asm("fma.rn.f32x2 %0, %1, %2, %0;" : "+l"(d) : "l"(a), "l"(b));
}
__device__ __forceinline__ ull add2(ull a, ull b) {
    ull d; asm("add.rn.f32x2 %0, %1, %2;" : "=l"(d) : "l"(a), "l"(b)); return d;
}
__device__ __forceinline__ ull mul2(ull a, ull b) {
    ull d; asm("mul.rn.f32x2 %0, %1, %2;" : "=l"(d) : "l"(a), "l"(b)); return d;
}
__device__ __forceinline__ ull dup2(float x) {
    ull d; asm("mov.b64 %0, {%1, %1};" : "=l"(d) : "f"(x)); return d;
}
__device__ __forceinline__ float2 unpack2(ull v) {
    float2 r; asm("mov.b64 {%0, %1}, %2;" : "=f"(r.x), "=f"(r.y) : "l"(v)); return r;
}
__device__ __forceinline__ float mishf(float v) {
    return v * tanhf(log1pf(expf(v)));
}

// ---------------- kernels ----------------

// h = x @ Wemb^T
__global__ void k_embed(const float* __restrict__ x, const float* __restrict__ Wemb) {
    __shared__ float sW[EMB * ATOM_F];
    for (int i = threadIdx.x; i < EMB * ATOM_F; i += blockDim.x) sW[i] = Wemb[i];
    __syncthreads();
    int node = blockIdx.x * blockDim.x + threadIdx.x;
    if (node >= NN) return;
    float4 xv[8];
    const float4* x4 = (const float4*)(x + (size_t)node * ATOM_F);
#pragma unroll
    for (int f = 0; f < 8; f++) xv[f] = __ldg(&x4[f]);
    float4* out4 = (float4*)(g_h + (size_t)node * EMB);
    for (int j = 0; j < EMB; j += 4) {
        float accs[4];
#pragma unroll
        for (int c = 0; c < 4; c++) {
            const float4* w = (const float4*)(sW + (j + c) * ATOM_F);
            float a = 0.f, b = 0.f;
#pragma unroll
            for (int f = 0; f < 8; f++) {
                float4 wv = w[f];
                a = fmaf(xv[f].x, wv.x, a);
                b = fmaf(xv[f].y, wv.y, b);
                a = fmaf(xv[f].z, wv.z, a);
                b = fmaf(xv[f].w, wv.w, b);
            }
            accs[c] = a + b;
        }
        out4[j >> 2] = make_float4(accs[0], accs[1], accs[2], accs[3]);
    }
}

// zero ideg + BN stat buffers
__global__ void k_zero_init() {
    int t = blockIdx.x * blockDim.x + threadIdx.x;
    if (t < NN) g_ideg[t] = 0;
    if (t < 4 * EMB) g_stats[t] = 0.f;
}

__global__ void k_hist(const int* __restrict__ ei) {
    int e = blockIdx.x * blockDim.x + threadIdx.x;
    if (e >= EE) return;
    atomicAdd(&g_ideg[__ldg(&ei[EE + e])], 1);
}

// multi-block exclusive scan: phase 1 (per-block scan + block sums)
__global__ void k_scan1() {
    __shared__ int s[256];
    int tid = threadIdx.x;
    int i = blockIdx.x * 256 + tid;
    int v = (i < NN) ? g_ideg[i] : 0;
    s[tid] = v;
    __syncthreads();
#pragma unroll
    for (int off = 1; off < 256; off <<= 1) {
        int add = (tid >= off) ? s[tid - off] : 0;
        __syncthreads();
        s[tid] += add;
        __syncthreads();
    }
    if (i < NN) g_rowptr[i] = s[tid] - v;
    if (tid == 255) g_bsum[blockIdx.x] = s[255];
}

__global__ void k_scan2() {
    __shared__ int s[256];
    int tid = threadIdx.x;
    const int nb = (NN + 255) / 256;
    int v = (tid < nb) ? g_bsum[tid] : 0;
    s[tid] = v;
    __syncthreads();
#pragma unroll
    for (int off = 1; off < 256; off <<= 1) {
        int add = (tid >= off) ? s[tid - off] : 0;
        __syncthreads();
        s[tid] += add;
        __syncthreads();
    }
    g_boff[tid] = s[tid] - v;
}

__global__ void k_scan3() {
    int i = blockIdx.x * 256 + threadIdx.x;
    if (i < NN) {
        int r = g_rowptr[i] + g_boff[blockIdx.x];
        g_rowptr[i] = r;
        g_cursor[i] = r;
    }
    if (i == 0) g_rowptr[NN] = EE;
}

__global__ void k_fill(const int* __restrict__ ei) {
    int e = blockIdx.x * blockDim.x + threadIdx.x;
    if (e >= EE) return;
    int dst = __ldg(&ei[EE + e]);
    int src = __ldg(&ei[e]);
    int pos = atomicAdd(&g_cursor[dst], 1);
    g_csrc[pos] = src;
    g_ceid[pos] = e;
}

// sea[n] = sum of incident edge_attr; deg[n] = count   (16 threads per node)
__global__ void k_pre(const float* __restrict__ ea) {
    int t = blockIdx.x * blockDim.x + threadIdx.x;
    int n = t >> 4;
    if (n >= NN) return;
    int lane = t & 15;
    int beg = g_rowptr[n], end = g_rowptr[n + 1];
    if (lane == 0) g_deg[n] = (float)(end - beg);
    float acc = 0.f;
    for (int i = beg; i < end; i++) {
        int e = __ldg(&g_ceid[i]);
        acc += __ldg(&ea[(size_t)e * BOND_F + lane]);
    }
    g_sea[(size_t)n * BOND_F + lane] = acc;
}

// pull aggregation: aggr[n] = h[n] + sum_{src} h[src]
// 16 threads per node, one float4 per thread per edge -> 25k warps, wide loads.
__global__ void __launch_bounds__(256) k_aggr(int base, int count) {
    int t = blockIdx.x * blockDim.x + threadIdx.x;
    int idx = t >> 4;
    if (idx >= count) return;
    int n = base + idx;
    int lane = t & 15;
    const float4* h4 = (const float4*)g_h;
    int beg = __ldg(&g_rowptr[n]), end = __ldg(&g_rowptr[n + 1]);
    float4 a0 = h4[(size_t)n * 16 + lane];   // self-loop
    float4 a1 = make_float4(0.f, 0.f, 0.f, 0.f);
    int i = beg;
    for (; i + 1 < end; i += 2) {
        int s0 = __ldg(&g_csrc[i]);
        int s1 = __ldg(&g_csrc[i + 1]);
        float4 v0 = __ldg(&h4[(size_t)s0 * 16 + lane]);
        float4 v1 = __ldg(&h4[(size_t)s1 * 16 + lane]);
        a0.x += v0.x; a0.y += v0.y; a0.z += v0.z; a0.w += v0.w;
        a1.x += v1.x; a1.y += v1.y; a1.z += v1.z; a1.w += v1.w;
    }
    if (i < end) {
        int s0 = __ldg(&g_csrc[i]);
        float4 v0 = __ldg(&h4[(size_t)s0 * 16 + lane]);
        a0.x += v0.x; a0.y += v0.y; a0.z += v0.z; a0.w += v0.w;
    }
    ((float4*)g_aggr)[(size_t)n * 16 + lane] =
        make_float4(a0.x + a1.x, a0.y + a1.y, a0.z + a1.z, a0.w + a1.w);
}

// fused MLP (packed f32x2) + fused BN statistics, over nodes [base, base+count)
// z = aggr + Sea@We^T + (deg+1)*be ; hid = relu(z@W1^T + b1) ; hn = hid@W2^T
// (b2 dropped: cancels under BatchNorm mean subtraction)
__global__ void __launch_bounds__(128, 2) k_mlp(
    const float* __restrict__ W1, const float* __restrict__ b1,
    const float* __restrict__ W2, const float* __restrict__ We,
    const float* __restrict__ be, int l, int base, int count)
{
    extern __shared__ float sm[];
    float* sW1  = sm;                 // [128][64]
    float* sW2T = sm + 8192;          // [128][64]
    float* sWeT = sm + 16384;         // [16][64]
    float* sb1  = sm + 17408;         // [128]
    float* sbe  = sm + 17536;         // [64]
    float* sred = sm + 17600;         // [4][128]

    int tid = threadIdx.x;
    const float* W1l = W1 + (size_t)l * 8192;
    const float* W2l = W2 + (size_t)l * 8192;
    for (int i = tid; i < 8192; i += 128) sW1[i] = W1l[i];
    for (int i = tid; i < 8192; i += 128) {
        int j = i >> 7, k = i & 127;
        sW2T[k * 64 + j] = W2l[i];
    }
    for (int i = tid; i < 1024; i += 128) {
        int q = i >> 6, j = i & 63;
        sWeT[i] = We[(size_t)l * 1024 + j * 16 + q];
    }
    if (tid < 128) sb1[tid] = b1[(size_t)l * 128 + tid];
    if (tid < 64)  sbe[tid] = be[(size_t)l * 64 + tid];
    __syncthreads();

    int node = base + blockIdx.x * 128 + tid;
    const bool valid = (node < base + count);
    int nc = valid ? node : base;

    // ---- prologue: z (packed over j-pairs) ----
    ull z2[32];
    {
        const ull* a2 = (const ull*)(g_aggr + (size_t)nc * EMB);
#pragma unroll
        for (int p = 0; p < 32; p++) z2[p] = a2[p];
    }
    {
        ull dp2 = dup2(g_deg[nc] + 1.0f);
        const ull* be2 = (const ull*)sbe;
#pragma unroll
        for (int p = 0; p < 32; p++) fma2(z2[p], dp2, be2[p]);
    }
    {
        float seav[16];
        const float4* sr = (const float4*)(g_sea + (size_t)nc * BOND_F);
#pragma unroll
        for (int q4 = 0; q4 < 4; q4++) {
            float4 v = sr[q4];
            seav[q4 * 4 + 0] = v.x; seav[q4 * 4 + 1] = v.y;
            seav[q4 * 4 + 2] = v.z; seav[q4 * 4 + 3] = v.w;
        }
#pragma unroll
        for (int q = 0; q < 16; q++) {
            ull sq = dup2(seav[q]);
            const ull* wq = (const ull*)(sWeT + q * 64);
#pragma unroll
            for (int p = 0; p < 32; p++) fma2(z2[p], sq, wq[p]);
        }
    }

    // ---- main loop over hidden units ----
    ull hn2[32];
#pragma unroll
    for (int p = 0; p < 32; p++) hn2[p] = 0ull;

#pragma unroll 2
    for (int k = 0; k < 128; k++) {
        const ulonglong2* wr = (const ulonglong2*)(sW1 + (k << 6));
        ull a = 0ull, b = 0ull, c = 0ull, d = 0ull;
#pragma unroll
        for (int p = 0; p < 8; p++) {
            ulonglong2 wA = wr[2 * p];
            ulonglong2 wB = wr[2 * p + 1];
            fma2(a, z2[4 * p + 0], wA.x);
            fma2(b, z2[4 * p + 1], wA.y);
            fma2(c, z2[4 * p + 2], wB.x);
            fma2(d, z2[4 * p + 3], wB.y);
        }
        float2 s = unpack2(add2(add2(a, b), add2(c, d)));
        float acc = fmaxf((s.x + s.y) + sb1[k], 0.0f);
        ull av = dup2(acc);
        const ulonglong2* w2r = (const ulonglong2*)(sW2T + (k << 6));
#pragma unroll
        for (int p = 0; p < 16; p++) {
            ulonglong2 w = w2r[p];
            fma2(hn2[2 * p + 0], av, w.x);
            fma2(hn2[2 * p + 1], av, w.y);
        }
    }

    if (valid) {
        ulonglong2* o = (ulonglong2*)(g_hn + (size_t)node * EMB);
#pragma unroll
        for (int p = 0; p < 16; p++)
            o[p] = make_ulonglong2(hn2[2 * p], hn2[2 * p + 1]);
    }

    // ---- fused BN statistics (packed warp reduction) ----
    int lane = tid & 31, wrp = tid >> 5;
#pragma unroll
    for (int p = 0; p < 32; p++) {
        ull s2 = valid ? hn2[p] : 0ull;
        ull q2 = mul2(s2, s2);
#pragma unroll
        for (int off = 16; off; off >>= 1) {
            s2 = add2(s2, __shfl_down_sync(0xffffffffu, s2, off));
            q2 = add2(q2, __shfl_down_sync(0xffffffffu, q2, off));
        }
        if (lane == 0) {
            float2 sv = unpack2(s2), qv = unpack2(q2);
            sred[wrp * 128 + 2 * p]     = sv.x;
            sred[wrp * 128 + 2 * p + 1] = sv.y;
            sred[wrp * 128 + 64 + 2 * p]     = qv.x;
            sred[wrp * 128 + 64 + 2 * p + 1] = qv.y;
        }
    }
    __syncthreads();
    if (tid < 128) {
        float v = sred[tid] + sred[128 + tid] + sred[256 + tid] + sred[384 + tid];
        atomicAdd(&g_stats[((l & 1) << 7) + tid], v);
    }
}

// BN (batch stats) + optional mish; writes g_h or d_out.
// Also zeroes the other-parity stats buffer for the next layer.
__global__ void k_finalize(const float* __restrict__ gamma, const float* __restrict__ beta,
                           int l, int domish, float* __restrict__ out)
{
    int t = blockIdx.x * blockDim.x + threadIdx.x;
    if (blockIdx.x == 0 && threadIdx.x < 128)
        g_stats[(((l + 1) & 1) << 7) + threadIdx.x] = 0.f;
    if (t >= NN * (EMB / 4)) return;
    int j4 = (t & 15) * 4;
    const float* st = g_stats + ((l & 1) << 7);
    float4 v = ((const float4*)g_hn)[t];
    float vv[4] = {v.x, v.y, v.z, v.w};
    float r[4];
    const float inv_n = 1.0f / (float)NN;
#pragma unroll
    for (int c = 0; c < 4; c++) {
        int j = j4 + c;
        float s = st[j], q = st[64 + j];
        float mu = s * inv_n;
        float var = fmaf(q, inv_n, -mu * mu);
        float inv = rsqrtf(var + 1e-5f);
        float val = (vv[c] - mu) * inv * __ldg(&gamma[l * 64 + j]) + __ldg(&beta[l * 64 + j]);
        if (domish) val = mishf(val);
        r[c] = val;
    }
    float4 o = make_float4(r[0], r[1], r[2], r[3]);
    if (out) ((float4*)out)[t] = o;
    else     ((float4*)g_h)[t] = o;
}

// ---------------- launch ----------------
extern "C" void kernel_launch(void* const* d_in, const int* in_sizes, int n_in,
                              void* d_out, int out_size)
{
    const float* x     = (const float*)d_in[0];
    const float* ea    = (const float*)d_in[1];
    const float* Wemb  = (const float*)d_in[2];
    const float* W1    = (const float*)d_in[3];
    const float* b1    = (const float*)d_in[4];
    const float* W2    = (const float*)d_in[5];
    // d_in[6] = b2 : provably cancelled by BatchNorm mean subtraction
    const float* We    = (const float*)d_in[7];
    const float* be    = (const float*)d_in[8];
    const float* gamma = (const float*)d_in[9];
    const float* beta  = (const float*)d_in[10];
    const int*   ei    = (const int*)d_in[11];
    float* out = (float*)d_out;

    // one-time side stream + events for fork-join (reused every call; same
    // work is enqueued on every call, so behavior is deterministic)
    static cudaStream_t s1 = nullptr;
    static cudaEvent_t evF = nullptr, evJ = nullptr;
    if (!s1) {
        cudaStreamCreateWithFlags(&s1, cudaStreamNonBlocking);
        cudaEventCreateWithFlags(&evF, cudaEventDisableTiming);
        cudaEventCreateWithFlags(&evJ, cudaEventDisableTiming);
    }

    const int MLP_SMEM = (8192 + 8192 + 1024 + 128 + 64 + 512) * 4; // 72448 B
    cudaFuncSetAttribute(k_mlp, cudaFuncAttributeMaxDynamicSharedMemorySize, MLP_SMEM);

    const int NB = (NN + 255) / 256;              // 196
    const int FB = (NN * (EMB / 4) + 255) / 256;  // 3125

    const int MID = 25088;            // 196 * 128, half-point for node split
    const int CNT1 = NN - MID;        // 24912

    k_embed<<<(NN + 127) / 128, 128>>>(x, Wemb);

    // CSR build (once)
    k_zero_init<<<NB, 256>>>();
    k_hist<<<(EE + 255) / 256, 256>>>(ei);
    k_scan1<<<NB, 256>>>();
    k_scan2<<<1, 256>>>();
    k_scan3<<<NB, 256>>>();
    k_fill<<<(EE + 255) / 256, 256>>>(ei);
    k_pre<<<(NN * 16 + 255) / 256, 256>>>(ea);

    for (int l = 0; l < NLAYER; l++) {
        int domish = (l < NLAYER - 1) ? 1 : 0;
        float* o = (l == NLAYER - 1) ? out : nullptr;

        // fork: half1 on side stream
        cudaEventRecord(evF, 0);
        cudaStreamWaitEvent(s1, evF, 0);

        k_aggr<<<(MID * 16 + 255) / 256, 256>>>(0, MID);
        k_mlp<<<MID / 128, 128, MLP_SMEM>>>(W1, b1, W2, We, be, l, 0, MID);

        k_aggr<<<(CNT1 * 16 + 255) / 256, 256, 0, s1>>>(MID, CNT1);
        k_mlp<<<(CNT1 + 127) / 128, 128, MLP_SMEM, s1>>>(W1, b1, W2, We, be, l, MID, CNT1);

        // join
        cudaEventRecord(evJ, s1);
        cudaStreamWaitEvent(0, evJ, 0);

        k_finalize<<<FB, 256>>>(gamma, beta, l, domish, o);
    }
}